// round 2
// baseline (speedup 1.0000x reference)
#include <cuda_runtime.h>
#include <math.h>

#define THREADS 1024
#define VOCAB   32000
#define BATCH   16
#define DEC_T   128
#define ATTN_L  512
#define DMODEL  768
#define NHEADS  12

// ---------------- block reductions (32 warps fixed) ----------------

__device__ __forceinline__ float blockReduceSum(float v, volatile float* scratch) {
    int lane = threadIdx.x & 31;
    int w    = threadIdx.x >> 5;
#pragma unroll
    for (int o = 16; o; o >>= 1) v += __shfl_xor_sync(0xffffffffu, v, o);
    __syncthreads();                 // protect scratch reuse across calls
    if (lane == 0) scratch[w] = v;
    __syncthreads();
    if (w == 0) {
        v = scratch[lane];
#pragma unroll
        for (int o = 16; o; o >>= 1) v += __shfl_xor_sync(0xffffffffu, v, o);
        if (lane == 0) scratch[0] = v;
    }
    __syncthreads();
    return scratch[0];
}

__device__ __forceinline__ float blockReduceMax(float v, volatile float* scratch) {
    int lane = threadIdx.x & 31;
    int w    = threadIdx.x >> 5;
#pragma unroll
    for (int o = 16; o; o >>= 1) v = fmaxf(v, __shfl_xor_sync(0xffffffffu, v, o));
    __syncthreads();
    if (lane == 0) scratch[w] = v;
    __syncthreads();
    if (w == 0) {
        v = scratch[lane];
#pragma unroll
        for (int o = 16; o; o >>= 1) v = fmaxf(v, __shfl_xor_sync(0xffffffffu, v, o));
        if (lane == 0) scratch[0] = v;
    }
    __syncthreads();
    return scratch[0];
}

// ---------------- fused pointer-generator kernel ----------------
// One CTA per (b, t) row. The full 32000-float vocab row is staged in
// dynamic shared memory so final_output is read from HBM exactly once.
//
// out[v] = log( pg * softmax(fin)[v] + (1-pg) * attn_softmax scattered )
//        = log( e[v] + c_adj[v] ) + log(pg) - log(S)
// with e[v] = exp(fin[v]-max) held in smem and c_adj = c * S / pg.

__global__ void __launch_bounds__(THREADS, 1)
pg_fused_kernel(const float* __restrict__ dec,     // [B, T, D]
                const float* __restrict__ fin,     // [B, T, V]
                const float* __restrict__ attn,    // [B, H, T, L]
                const int*   __restrict__ enc,     // [B, L]
                const float* __restrict__ Wpg,     // [D, 1]
                const float* __restrict__ bpg,     // [1]
                float*       __restrict__ out)     // [B, T, V]
{
    extern __shared__ float smem[];
    float* row  = smem;            // VOCAB floats (e-values)
    __shared__ float scratch[32];

    const int tid = threadIdx.x;
    const int bt  = blockIdx.x;          // 0 .. B*T-1
    const int b   = bt / DEC_T;
    const int t   = bt - b * DEC_T;

    // ---- 1. p_gen = sigmoid(dec_row . W_pg + b) ----
    const float* drow = dec + (size_t)bt * DMODEL;
    float acc = 0.f;
    for (int i = tid; i < DMODEL; i += THREADS) acc += drow[i] * Wpg[i];
    const float dot = blockReduceSum(acc, scratch);
    const float pg  = 1.f / (1.f + __expf(-(dot + bpg[0])));

    // ---- 2. load vocab row into smem (float4), track max ----
    const float4* frow4 = (const float4*)(fin + (size_t)bt * VOCAB);
    float4*       row4  = (float4*)row;
    float mx = -INFINITY;
    for (int i = tid; i < VOCAB / 4; i += THREADS) {
        float4 v = frow4[i];
        row4[i]  = v;
        mx = fmaxf(mx, fmaxf(fmaxf(v.x, v.y), fmaxf(v.z, v.w)));
    }
    mx = blockReduceMax(mx, scratch);

    // ---- 3. exp in place, reduce sum S ----
    float s = 0.f;
    for (int i = tid; i < VOCAB / 4; i += THREADS) {
        float4 v = row4[i];
        v.x = __expf(v.x - mx);
        v.y = __expf(v.y - mx);
        v.z = __expf(v.z - mx);
        v.w = __expf(v.w - mx);
        row4[i] = v;
        s += v.x + v.y + v.z + v.w;
    }
    const float S = blockReduceSum(s, scratch);

    // ---- 4. attention: mean over heads, softmax over L=512 ----
    const float* abase = attn + ((size_t)b * NHEADS * DEC_T + t) * ATTN_L;
    float aval = 0.f;
    float am   = -INFINITY;
    if (tid < ATTN_L) {
        float hs = 0.f;
#pragma unroll
        for (int h = 0; h < NHEADS; h++)
            hs += abase[(size_t)h * DEC_T * ATTN_L + tid];
        aval = hs * (1.f / NHEADS);
        am   = aval;
    }
    am = blockReduceMax(am, scratch);
    float ae = 0.f;
    if (tid < ATTN_L) ae = __expf(aval - am);
    const float asum = blockReduceSum(ae, scratch);

    // ---- 5. scatter-add attention mass into the e-row (exp units) ----
    // contribution to final dist: (1-pg) * ae/asum  ->  e-units: * S/pg
    const float coef = (1.f - pg) * S / (asum * pg);
    if (tid < ATTN_L) {
        const int id = enc[b * ATTN_L + tid];
        atomicAdd(&row[id], ae * coef);
    }
    __syncthreads();

    // ---- 6. out = log(e + c_adj) + log(pg) - log(S) ----
    const float lco = __logf(pg) - __logf(S);
    float4* orow4 = (float4*)(out + (size_t)bt * VOCAB);
    for (int i = tid; i < VOCAB / 4; i += THREADS) {
        float4 v = row4[i];
        v.x = __logf(v.x) + lco;
        v.y = __logf(v.y) + lco;
        v.z = __logf(v.z) + lco;
        v.w = __logf(v.w) + lco;
        orow4[i] = v;
    }
}

extern "C" void kernel_launch(void* const* d_in, const int* in_sizes, int n_in,
                              void* d_out, int out_size) {
    const float* dec  = (const float*)d_in[0];   // dec_output      [16,128,768]
    const float* fin  = (const float*)d_in[1];   // final_output    [16,128,32000]
    const float* attn = (const float*)d_in[2];   // attention_weights [16,12,128,512]
    const int*   enc  = (const int*)  d_in[3];   // encoder_input   [16,512]
    const float* Wpg  = (const float*)d_in[4];   // W_pg            [768,1]
    const float* bpg  = (const float*)d_in[5];   // b_pg            [1]
    float*       out  = (float*)d_out;           // [16,128,32000] f32

    const int smem_bytes = VOCAB * (int)sizeof(float);   // 128000 B
    cudaFuncSetAttribute(pg_fused_kernel,
                         cudaFuncAttributeMaxDynamicSharedMemorySize, smem_bytes);

    pg_fused_kernel<<<BATCH * DEC_T, THREADS, smem_bytes>>>(
        dec, fin, attn, enc, Wpg, bpg, out);
}

// round 3
// speedup vs baseline: 1.3197x; 1.3197x over previous
#include <cuda_runtime.h>
#include <math.h>

#define THREADS 1024
#define VOCAB   32000
#define BATCH   16
#define DEC_T   128
#define ATTN_L  512
#define DMODEL  768
#define NHEADS  12
#define HASHSZ  1024   // == THREADS, power of 2, >= ATTN_L

// ---------------- block reductions (32 warps fixed) ----------------

__device__ __forceinline__ float blockReduceSum(float v, volatile float* scratch) {
    int lane = threadIdx.x & 31;
    int w    = threadIdx.x >> 5;
#pragma unroll
    for (int o = 16; o; o >>= 1) v += __shfl_xor_sync(0xffffffffu, v, o);
    __syncthreads();
    if (lane == 0) scratch[w] = v;
    __syncthreads();
    if (w == 0) {
        v = scratch[lane];
#pragma unroll
        for (int o = 16; o; o >>= 1) v += __shfl_xor_sync(0xffffffffu, v, o);
        if (lane == 0) scratch[0] = v;
    }
    __syncthreads();
    return scratch[0];
}

__device__ __forceinline__ float blockReduceMax(float v, volatile float* scratch) {
    int lane = threadIdx.x & 31;
    int w    = threadIdx.x >> 5;
#pragma unroll
    for (int o = 16; o; o >>= 1) v = fmaxf(v, __shfl_xor_sync(0xffffffffu, v, o));
    __syncthreads();
    if (lane == 0) scratch[w] = v;
    __syncthreads();
    if (w == 0) {
        v = scratch[lane];
#pragma unroll
        for (int o = 16; o; o >>= 1) v = fmaxf(v, __shfl_xor_sync(0xffffffffu, v, o));
        if (lane == 0) scratch[0] = v;
    }
    __syncthreads();
    return scratch[0];
}

// ---------------- fused pointer-generator kernel (2-pass, no big smem) ----
// One CTA per (b, t) row.
//   non-scattered v: out[v] = fin[v] - M + log(pg) - log(S)   (pure add!)
//   scattered id   : out[id] = log(exp(fin[id]-M) + c_id) + log(pg) - log(S)
// with c_id = sum_j[enc_j==id] ae_j * (1-pg)*S/(asum*pg), aggregated in a
// small shared-memory hash table.

__global__ void __launch_bounds__(THREADS, 2)
pg_fused_kernel(const float* __restrict__ dec,     // [B, T, D]
                const float* __restrict__ fin,     // [B, T, V]
                const float* __restrict__ attn,    // [B, H, T, L]
                const int*   __restrict__ enc,     // [B, L]
                const float* __restrict__ Wpg,     // [D, 1]
                const float* __restrict__ bpg,     // [1]
                float*       __restrict__ out)     // [B, T, V]
{
    __shared__ float scratch[32];
    __shared__ int   hid [HASHSZ];
    __shared__ float hval[HASHSZ];

    const int tid = threadIdx.x;
    const int bt  = blockIdx.x;              // 0 .. B*T-1
    const int b   = bt >> 7;                 // / DEC_T
    const int t   = bt & (DEC_T - 1);

    hid [tid] = -1;
    hval[tid] = 0.f;

    // ---- 1. p_gen = sigmoid(dec_row . W_pg + b) ----
    const float* drow = dec + (size_t)bt * DMODEL;
    float acc = 0.f;
    for (int i = tid; i < DMODEL; i += THREADS) acc += drow[i] * Wpg[i];
    const float dot = blockReduceSum(acc, scratch);
    const float pg  = 1.f / (1.f + __expf(-(dot + bpg[0])));

    // ---- 2. online softmax stats over the vocab row (ONE DRAM read) ----
    const float4* frow4 = (const float4*)(fin + (size_t)bt * VOCAB);
    float m = -INFINITY, s = 0.f;
    for (int i = tid; i < VOCAB / 4; i += THREADS) {
        float4 v = frow4[i];
        float lm = fmaxf(fmaxf(v.x, v.y), fmaxf(v.z, v.w));
        if (lm > m) { s *= __expf(m - lm); m = lm; }
        s += __expf(v.x - m) + __expf(v.y - m) + __expf(v.z - m) + __expf(v.w - m);
    }
    const float M = blockReduceMax(m, scratch);
    const float S = blockReduceSum(s * __expf(m - M), scratch);

    // ---- 3. attention: mean over heads, softmax over L=512 ----
    const float* abase = attn + ((size_t)b * NHEADS * DEC_T + t) * ATTN_L;
    float aval = 0.f, am = -INFINITY;
    if (tid < ATTN_L) {
        float hs = 0.f;
#pragma unroll
        for (int h = 0; h < NHEADS; h++)
            hs += __ldcs(&abase[(size_t)h * DEC_T * ATTN_L + tid]);
        aval = hs * (1.f / NHEADS);
        am   = aval;
    }
    am = blockReduceMax(am, scratch);
    float ae = (tid < ATTN_L) ? __expf(aval - am) : 0.f;
    const float asum = blockReduceSum(ae, scratch);

    // ---- 4. aggregate duplicate vocab ids in smem hash (CAS + add) ----
    if (tid < ATTN_L) {
        const int id = enc[b * ATTN_L + tid];
        int h = id & (HASHSZ - 1);
        for (;;) {
            int prev = atomicCAS(&hid[h], -1, id);
            if (prev == -1 || prev == id) { atomicAdd(&hval[h], ae); break; }
            h = (h + 1) & (HASHSZ - 1);
        }
    }

    // ---- 5. bulk output: fin - M + lco  (fin re-read hits L2) ----
    const float lco = __logf(pg) - __logf(S);
    const float c1  = lco - M;
    float4* orow4 = (float4*)(out + (size_t)bt * VOCAB);
    for (int i = tid; i < VOCAB / 4; i += THREADS) {
        float4 v = frow4[i];
        v.x += c1; v.y += c1; v.z += c1; v.w += c1;
        __stcs(&orow4[i], v);     // streaming store: don't pollute L2
    }
    __syncthreads();              // order bulk stores before fixup rewrites

    // ---- 6. fixup the <=512 scattered ids ----
    const float coef = (1.f - pg) * S / (asum * pg);
    const int id = hid[tid];
    if (id >= 0) {
        const float c = hval[tid] * coef;
        const float e = __expf(fin[(size_t)bt * VOCAB + id] - M);
        out[(size_t)bt * VOCAB + id] = __logf(e + c) + lco;
    }
}

extern "C" void kernel_launch(void* const* d_in, const int* in_sizes, int n_in,
                              void* d_out, int out_size) {
    const float* dec  = (const float*)d_in[0];   // [16,128,768]
    const float* fin  = (const float*)d_in[1];   // [16,128,32000]
    const float* attn = (const float*)d_in[2];   // [16,12,128,512]
    const int*   enc  = (const int*)  d_in[3];   // [16,512]
    const float* Wpg  = (const float*)d_in[4];   // [768,1]
    const float* bpg  = (const float*)d_in[5];   // [1]
    float*       out  = (float*)d_out;           // [16,128,32000]

    pg_fused_kernel<<<BATCH * DEC_T, THREADS>>>(dec, fin, attn, enc, Wpg, bpg, out);
}